// round 5
// baseline (speedup 1.0000x reference)
#include <cuda_runtime.h>
#include <cuda_bf16.h>
#include <cstdint>

#define NN   128
#define DD   128
#define EE   128
#define NG   8
#define VDIM 300
#define VSPLIT 8          // CTAs per graph in k_vec
#define VWARPS_CTA 8      // warps per k_vec CTA
#define VWARPS (VSPLIT * VWARPS_CTA)

// ---------------- device scratch (allocation-free) ----------------
__device__ float g_base[NN * DD];
__device__ float g_vacc[NG][NN * DD];
__device__ float g_vpos[NG][DD];
__device__ float g_u[NG][NN][DD];
__device__ float g_y0[NG][EE * DD];
__device__ float g_w2[NG][DD];
__device__ float g_cconst[NG];
__device__ float g_dscore;
__device__ int   g_sync[NG];

__device__ int g_par[NG][NN];
__device__ int g_cc[NG][NN];
__device__ int g_ord[NG][NN];
__device__ int g_lvlstart[NG][NN + 2];
__device__ int g_maxh[NG];
__device__ int g_plen[NG];
__device__ int g_plist[NG][NN];
__device__ int g_pedge[NG][NN];

// =============== tree parse: 128 threads per graph ===============
__global__ void k_parse(const int* __restrict__ graphs,
                        const int* __restrict__ edges,
                        const int* __restrict__ posp) {
    __shared__ int s_par[NN], s_h[NN], s_cc[NN];
    __shared__ int s_cnt[NN + 1], s_cur[NN + 1];
    __shared__ unsigned char s_inpath[NN];
    __shared__ unsigned s_rootmask[4];
    __shared__ int s_changed, s_maxh;

    int g = blockIdx.x, t = threadIdx.x;
    int off = graphs[g * NN + t];
    bool isroot = (off == 0);
    int par = isroot ? -1 : ((t + off < NN) ? t + off : -1);
    unsigned bm = __ballot_sync(0xffffffffu, isroot);
    if ((t & 31) == 0) s_rootmask[t >> 5] = bm;
    s_par[t] = par;
    s_h[t] = 0; s_cc[t] = 0; s_inpath[t] = 0;
    if (t == 0) { s_changed = 0; s_maxh = 0; g_sync[g] = 0; }
    __syncthreads();

    if (t == 0) {
        // chain roots (ascending): parents[r_i] = offset r_{i+1}
        int prev = -1;
        for (int w4 = 0; w4 < 4; w4++) {
            unsigned mm = s_rootmask[w4];
            while (mm) {
                int b = __ffs(mm) - 1; mm &= mm - 1;
                int r = w4 * 32 + b;
                if (prev >= 0) { int p = prev + r; s_par[prev] = (p < NN) ? p : -1; }
                prev = r;
            }
        }
        s_par[prev] = -1;   // final root
    }
    __syncthreads();
    par = s_par[t];
    if (par >= 0) atomicAdd(&s_cc[par], 1);
    __syncthreads();

    // heights via relaxation (converges in <= maxh rounds)
    for (;;) {
        if (t == 0) s_changed = 0;
        __syncthreads();
        if (par >= 0) {
            int nh = s_h[t] + 1;
            if (nh > s_h[par]) { atomicMax(&s_h[par], nh); s_changed = 1; }
        }
        __syncthreads();
        int ch = s_changed;
        __syncthreads();
        if (!ch) break;
    }

    if (t == 0) {
        int plen = 0, p = *posp;
        while (p >= 0) {
            s_inpath[p] = 1;
            g_plist[g][plen] = p;
            g_pedge[g][plen] = edges[p];
            plen++;
            p = s_par[p];
        }
        g_plen[g] = plen;
    }
    if (t <= NN) s_cnt[t] = 0;
    __syncthreads();

    bool np = !s_inpath[t];
    int h = s_h[t];
    if (np) { atomicAdd(&s_cnt[h], 1); atomicMax(&s_maxh, h); }
    __syncthreads();
    if (t == 0) {
        int maxh = s_maxh, run = 0;
        for (int l = 0; l <= maxh + 1; l++) {
            g_lvlstart[g][l] = run; s_cur[l] = run;
            if (l <= maxh) run += s_cnt[l];
        }
        g_maxh[g] = maxh;
    }
    __syncthreads();
    if (np) { int slot = atomicAdd(&s_cur[h], 1); g_ord[g][slot] = t; }
    g_par[g][t] = s_par[t];
    g_cc[g][t] = s_cc[t];
}

// =============== base[n,k] = data_vecs[data[n]] @ dw + db ===============
__global__ void k_base(const int* __restrict__ data,
                       const float* __restrict__ dv,
                       const float* __restrict__ dw,
                       const float* __restrict__ db) {
    int n = blockIdx.x, k = threadIdx.x;
    const float* vr = dv + (size_t)data[n] * VDIM;
    float acc = db[k];
#pragma unroll 5
    for (int v = 0; v < VDIM; v++) acc += vr[v] * dw[v * DD + k];
    g_base[n * DD + k] = acc;
}

// =============== d_score ===============
__global__ void k_dscore(const int* __restrict__ posp,
                         const float* __restrict__ sdw,
                         const float* __restrict__ sb) {
    __shared__ float red[DD];
    int t = threadIdx.x;
    int pos = *posp;
    red[t] = g_base[pos * DD + t] * sdw[t];
    __syncthreads();
    for (int s = 64; s > 0; s >>= 1) {
        if (t < s) red[t] += red[t + s];
        __syncthreads();
    }
    if (t == 0) g_dscore = red[0] + sb[0];
}

// =============== per-graph barrier across VSPLIT CTAs ===============
__device__ __forceinline__ void graph_barrier(int g, int target) {
    __syncthreads();
    if (threadIdx.x == 0) {
        __threadfence();
        atomicAdd(&g_sync[g], 1);
        while (atomicAdd(&g_sync[g], 0) < target) { }
    }
    __syncthreads();
}

// =============== vector pass: VSPLIT CTAs per graph ===============
__global__ void __launch_bounds__(256)
k_vec(const int* __restrict__ edges,
      const float* __restrict__ ew,
      const float* __restrict__ eb) {
    __shared__ int s_par[NN], s_cc[NN], s_ord[NN];
    __shared__ int s_lvlstart[NN + 2];

    int g = blockIdx.x / VSPLIT, s = blockIdx.x % VSPLIT;
    int tid = threadIdx.x;

    if (tid < NN) {
        s_par[tid] = g_par[g][tid];
        s_cc[tid]  = g_cc[g][tid];
        s_ord[tid] = g_ord[g][tid];
    }
    if (tid < NN + 2) s_lvlstart[tid] = g_lvlstart[g][tid];

    // init vacc slice = base
    {
        const float4* src = (const float4*)g_base;
        float4* dst = (float4*)g_vacc[g];
        int i0 = s * 512;
#pragma unroll
        for (int i = tid; i < 512; i += 256) dst[i0 + i] = src[i0 + i];
    }
    int bstep = 1;
    graph_barrier(g, bstep * VSPLIT);

    int maxh = g_maxh[g];
    int wp = tid >> 5, lane = tid & 31;
    int gwarp = s * VWARPS_CTA + wp;
    int k0 = lane * 4;
    float* vacc = g_vacc[g];

    for (int L = 0; L <= maxh; L++) {
        int st = s_lvlstart[L], en = s_lvlstart[L + 1];
        int units = (en - st) << 2;
        for (int u = gwarp; u < units; u += VWARPS) {
            int node = s_ord[st + (u >> 2)];
            int chunk = u & 3;
            int p = s_par[node];
            if (p < 0) continue;
            int e = edges[node];
            bool hasch = (s_cc[node] > 0);
            const float* W = ew + (size_t)e * (DD * DD);
            float y0, y1, y2, y3;
            if (chunk == 0) {
                const float* b = eb + e * DD;
                y0 = b[k0]; y1 = b[k0 + 1]; y2 = b[k0 + 2]; y3 = b[k0 + 3];
            } else { y0 = y1 = y2 = y3 = 0.f; }
            int d0 = chunk * 32;
            const float* vsrc = vacc + node * DD;
#pragma unroll 8
            for (int d = d0; d < d0 + 32; d++) {
                float v = __ldcg(vsrc + d);
                if (hasch) v = fmaxf(v, 0.f);
                float4 w = __ldg((const float4*)(W + d * DD + k0));
                y0 += v * w.x; y1 += v * w.y; y2 += v * w.z; y3 += v * w.w;
            }
            float* dst = vacc + p * DD + k0;
            atomicAdd(dst + 0, y0); atomicAdd(dst + 1, y1);
            atomicAdd(dst + 2, y2); atomicAdd(dst + 3, y3);
        }
        bstep++;
        graph_barrier(g, bstep * VSPLIT);
    }

    // export path vectors (CTA 0 of each graph)
    if (s == 0 && tid < DD) {
        int plen = g_plen[g];
        int p0 = g_plist[g][0];
        float v = __ldcg(&vacc[p0 * DD + tid]);
        if (s_cc[p0] > 0) v = fmaxf(v, 0.f);
        g_vpos[g][tid] = v;
        for (int idx = 1; idx < plen; idx++)
            g_u[g][idx][tid] = __ldcg(&vacc[g_plist[g][idx] * DD + tid]);
    }
}

// =============== fold root transform into score vector ===============
__global__ void k_fold(const float* __restrict__ ew,
                       const float* __restrict__ eb,
                       const float* __restrict__ sw) {
    __shared__ float ss[DD];
    __shared__ float red[DD];
    int g = blockIdx.x, t = threadIdx.x;
    int er = g_pedge[g][g_plen[g] - 1];
    ss[t] = sw[t];
    __syncthreads();
    const float* W = ew + (size_t)er * (DD * DD);
    float acc = 0.f;
#pragma unroll 4
    for (int k = 0; k < DD; k++) acc += W[t * DD + k] * ss[k];
    g_w2[g][t] = acc;
    red[t] = eb[er * DD + t] * ss[t];
    __syncthreads();
    for (int s = 64; s > 0; s >>= 1) {
        if (t < s) red[t] += red[t + s];
        __syncthreads();
    }
    if (t == 0) g_cconst[g] = red[0];
}

// =============== step0: y0[g][e] = vpos[g] @ W[e] + b[e] (W read once) ===============
__global__ void __launch_bounds__(128)
k_step0(const float* __restrict__ ew,
        const float* __restrict__ eb) {
    __shared__ float s_v[NG * DD];
    int e = blockIdx.x, k = threadIdx.x;
    for (int idx = k; idx < NG * DD; idx += 128)
        s_v[idx] = g_vpos[idx >> 7][idx & 127];
    __syncthreads();
    float acc[NG];
#pragma unroll
    for (int g = 0; g < NG; g++) acc[g] = 0.f;
    const float* W = ew + (size_t)e * (DD * DD);
#pragma unroll 2
    for (int d = 0; d < DD; d++) {
        float w = __ldg(W + d * DD + k);
#pragma unroll
        for (int g = 0; g < NG; g++) acc[g] += s_v[g * DD + d] * w;
    }
    float b = eb[e * DD + k];
#pragma unroll
    for (int g = 0; g < NG; g++) g_y0[g][e * DD + k] = acc[g] + b;
}

// =============== path chains: 16 CTAs/graph, 8 chains/CTA, 2 chains/warp ===============
#define CPB 8      // chains per block
__global__ void __launch_bounds__(128)
k_chain(const float* __restrict__ ew,
        const float* __restrict__ eb,
        const float* __restrict__ sw,
        float* __restrict__ out) {
    __shared__ __align__(16) float s_mA[DD * 10];
    __shared__ __align__(16) float s_mB[DD * 10];
    __shared__ float s_w2[DD];

    int g = blockIdx.x >> 4, blk = blockIdx.x & 15;
    int e0 = blk * CPB;
    int wp = threadIdx.x >> 5, lane = threadIdx.x & 31;
    int k0 = lane * 4;
    int c0 = 2 * wp, c1 = 2 * wp + 1;
    int plen = g_plen[g];
    float dscore = g_dscore;

    if (plen == 1) {
        // out = dscore + y0[g][e] . sw
        float4 sv = *(const float4*)(sw + k0);
        const float* ya = &g_y0[g][(e0 + c0) * DD + k0];
        const float* yb = &g_y0[g][(e0 + c1) * DD + k0];
        float4 a = *(const float4*)ya, b = *(const float4*)yb;
        float p0 = a.x * sv.x + a.y * sv.y + a.z * sv.z + a.w * sv.w;
        float p1 = b.x * sv.x + b.y * sv.y + b.z * sv.z + b.w * sv.w;
        for (int off = 16; off; off >>= 1) {
            p0 += __shfl_xor_sync(0xffffffffu, p0, off);
            p1 += __shfl_xor_sync(0xffffffffu, p1, off);
        }
        if (lane == 0) {
            out[g * EE + e0 + c0] = dscore + p0;
            out[g * EE + e0 + c1] = dscore + p1;
        }
        return;
    }

    if (threadIdx.x < DD) s_w2[threadIdx.x] = g_w2[g][threadIdx.x];
    // init state i=1: m[c][d] = relu(y0[g][e0+c][d] + u1[d])
    {
        const float* u1 = &g_u[g][1][0];
        for (int idx = threadIdx.x; idx < CPB * DD; idx += 128) {
            int c = idx >> 7, d = idx & 127;
            float v = g_y0[g][(e0 + c) * DD + d] + u1[d];
            s_mA[d * 10 + c] = fmaxf(v, 0.f);
        }
    }
    __syncthreads();

    float* cur = s_mA;
    float* nxt = s_mB;
    for (int i = 2; i < plen; i++) {
        int eid = g_pedge[g][i - 1];
        const float* W = ew + (size_t)eid * (DD * DD);
        float4 bv = *(const float4*)(eb + eid * DD + k0);
        float a0 = bv.x, a1 = bv.y, a2 = bv.z, a3 = bv.w;
        float b0 = bv.x, b1 = bv.y, b2 = bv.z, b3 = bv.w;
#pragma unroll 4
        for (int d = 0; d < DD; d++) {
            float4 w = __ldg((const float4*)(W + d * DD + k0));
            float2 mm = *(const float2*)&cur[d * 10 + c0];
            a0 += mm.x * w.x; a1 += mm.x * w.y; a2 += mm.x * w.z; a3 += mm.x * w.w;
            b0 += mm.y * w.x; b1 += mm.y * w.y; b2 += mm.y * w.z; b3 += mm.y * w.w;
        }
        float4 u4 = *(const float4*)(&g_u[g][i][0] + k0);
        nxt[(k0 + 0) * 10 + c0] = fmaxf(u4.x + a0, 0.f);
        nxt[(k0 + 1) * 10 + c0] = fmaxf(u4.y + a1, 0.f);
        nxt[(k0 + 2) * 10 + c0] = fmaxf(u4.z + a2, 0.f);
        nxt[(k0 + 3) * 10 + c0] = fmaxf(u4.w + a3, 0.f);
        nxt[(k0 + 0) * 10 + c1] = fmaxf(u4.x + b0, 0.f);
        nxt[(k0 + 1) * 10 + c1] = fmaxf(u4.y + b1, 0.f);
        nxt[(k0 + 2) * 10 + c1] = fmaxf(u4.z + b2, 0.f);
        nxt[(k0 + 3) * 10 + c1] = fmaxf(u4.w + b3, 0.f);
        __syncthreads();
        float* tmp = cur; cur = nxt; nxt = tmp;
    }

    // final: sc_c = sum_k m[c][k] * w2[k]
    float p0 = 0.f, p1 = 0.f;
#pragma unroll
    for (int j = 0; j < 4; j++) {
        float w2v = s_w2[k0 + j];
        p0 += cur[(k0 + j) * 10 + c0] * w2v;
        p1 += cur[(k0 + j) * 10 + c1] * w2v;
    }
    for (int off = 16; off; off >>= 1) {
        p0 += __shfl_xor_sync(0xffffffffu, p0, off);
        p1 += __shfl_xor_sync(0xffffffffu, p1, off);
    }
    if (lane == 0) {
        float cc = g_cconst[g];
        out[g * EE + e0 + c0] = dscore + cc + p0;
        out[g * EE + e0 + c1] = dscore + cc + p1;
    }
}

// =============== launcher ===============
extern "C" void kernel_launch(void* const* d_in, const int* in_sizes, int n_in,
                              void* d_out, int out_size) {
    const int*   data   = (const int*)d_in[0];
    const int*   graphs = (const int*)d_in[2];
    const int*   edges  = (const int*)d_in[3];
    const int*   pos    = (const int*)d_in[4];
    const float* dv     = (const float*)d_in[5];
    const float* dw     = (const float*)d_in[6];
    const float* db     = (const float*)d_in[7];
    const float* ew     = (const float*)d_in[8];
    const float* ebias  = (const float*)d_in[9];
    const float* sew    = (const float*)d_in[10];
    const float* sdw    = (const float*)d_in[11];
    const float* sb     = (const float*)d_in[12];
    float* out = (float*)d_out;

    k_parse <<<NG, NN>>>(graphs, edges, pos);
    k_base  <<<NN, DD>>>(data, dv, dw, db);
    k_dscore<<<1, DD>>>(pos, sdw, sb);
    k_vec   <<<NG * VSPLIT, 256>>>(edges, ew, ebias);
    k_fold  <<<NG, DD>>>(ew, ebias, sew);
    k_step0 <<<EE, 128>>>(ew, ebias);
    k_chain <<<NG * 16, 128>>>(ew, ebias, sew, out);
}

// round 6
// speedup vs baseline: 1.5684x; 1.5684x over previous
#include <cuda_runtime.h>
#include <cuda_bf16.h>
#include <cstdint>

#define NN   128
#define DD   128
#define EE   128
#define NG   8
#define VDIM 300

// ---------------- device scratch (allocation-free) ----------------
__device__ float g_base[NN * DD];
__device__ float g_vacc[NG][NN * DD];
__device__ float g_y0[NG][EE * DD];
__device__ float g_w2[NG][DD];
__device__ float g_cconst[NG];
__device__ float g_dscore;
__device__ int   g_cnt[NG][NN];
__device__ int   g_par[NG][NN];
__device__ int   g_cc[NG][NN];
__device__ unsigned char g_inpath[NG][NN];
__device__ int   g_plen[NG];
__device__ int   g_plist[NG][NN];
__device__ int   g_pedge[NG][NN];

// =============== tree parse: 128 threads per graph ===============
__global__ void k_parse(const int* __restrict__ graphs,
                        const int* __restrict__ edges,
                        const int* __restrict__ posp) {
    __shared__ int s_par[NN];
    __shared__ int s_cc[NN];
    __shared__ unsigned char s_inp[NN];
    __shared__ unsigned s_rm[4];
    int g = blockIdx.x, t = threadIdx.x;
    int off = graphs[g * NN + t];
    bool isroot = (off == 0);
    int par = isroot ? -1 : ((t + off < NN) ? t + off : -1);
    unsigned bm = __ballot_sync(0xffffffffu, isroot);
    if ((t & 31) == 0) s_rm[t >> 5] = bm;
    s_par[t] = par; s_cc[t] = 0; s_inp[t] = 0;
    __syncthreads();
    if (t == 0) {
        // faithful root chaining (ascending): parents[r_i] value = r_{i+1}, pp = r_i + r_{i+1}
        int prev = -1;
        for (int w4 = 0; w4 < 4; w4++) {
            unsigned mm = s_rm[w4];
            while (mm) {
                int b = __ffs(mm) - 1; mm &= mm - 1;
                int r = w4 * 32 + b;
                if (prev >= 0) { int p = prev + r; s_par[prev] = (p < NN) ? p : -1; }
                prev = r;
            }
        }
        s_par[prev] = -1;   // final root
    }
    __syncthreads();
    par = s_par[t];
    if (par >= 0) atomicAdd(&s_cc[par], 1);
    __syncthreads();
    if (t == 0) {
        int plen = 0, p = *posp;
        while (p >= 0) {
            s_inp[p] = 1;
            g_plist[g][plen] = p;
            g_pedge[g][plen] = edges[p];
            plen++;
            p = s_par[p];
        }
        g_plen[g] = plen;
    }
    __syncthreads();
    g_par[g][t] = par;
    g_cc[g][t] = s_cc[t];
    g_inpath[g][t] = s_inp[t];
    g_cnt[g][t] = 0;
}

// =============== base + fanout: vacc[g][n] = base[n] ===============
__global__ void k_base(const int* __restrict__ data,
                       const float* __restrict__ dv,
                       const float* __restrict__ dw,
                       const float* __restrict__ db) {
    __shared__ float s_v[VDIM];
    int n = blockIdx.x, k = threadIdx.x;
    const float* vr = dv + (size_t)data[n] * VDIM;
    for (int i = k; i < VDIM; i += DD) s_v[i] = vr[i];
    __syncthreads();
    float acc = db[k];
#pragma unroll 10
    for (int v = 0; v < VDIM; v++) acc += s_v[v] * __ldg(dw + v * DD + k);
    g_base[n * DD + k] = acc;
#pragma unroll
    for (int g = 0; g < NG; g++) g_vacc[g][n * DD + k] = acc;
}

// =============== dataflow vector pass: 1 warp per (graph, node) ===============
__global__ void __launch_bounds__(256)
k_vecflow(const int* __restrict__ edges,
          const float* __restrict__ ew,
          const float* __restrict__ eb) {
    int w = (blockIdx.x << 3) + (threadIdx.x >> 5);   // 0..1023
    int lane = threadIdx.x & 31;
    int g = w >> 7, n = w & 127;

    if (g_inpath[g][n]) return;
    int p = g_par[g][n];
    if (p < 0) return;
    int cc = g_cc[g][n];
    int e = edges[n];

    if (cc > 0) {
        int tgt = cc * 32;
        if (lane == 0) {
            while (atomicAdd(&g_cnt[g][n], 0) < tgt) { }
        }
        __syncwarp();
        __threadfence();
    }

    // load this node's accumulated vector (L2-coherent), relu if internal
    float4 vv = __ldcg((const float4*)(&g_vacc[g][n * DD] + lane * 4));
    if (cc > 0) {
        vv.x = fmaxf(vv.x, 0.f); vv.y = fmaxf(vv.y, 0.f);
        vv.z = fmaxf(vv.z, 0.f); vv.w = fmaxf(vv.w, 0.f);
    }

    const float* W = ew + (size_t)e * (DD * DD) + lane * 4;
    float4 bb = *(const float4*)(eb + e * DD + lane * 4);
    float y0 = bb.x, y1 = bb.y, y2 = bb.z, y3 = bb.w;

#pragma unroll 4
    for (int dq = 0; dq < 32; dq++) {
        float a0 = __shfl_sync(0xffffffffu, vv.x, dq);
        float a1 = __shfl_sync(0xffffffffu, vv.y, dq);
        float a2 = __shfl_sync(0xffffffffu, vv.z, dq);
        float a3 = __shfl_sync(0xffffffffu, vv.w, dq);
        float4 w0 = __ldg((const float4*)(W + (4 * dq + 0) * DD));
        float4 w1 = __ldg((const float4*)(W + (4 * dq + 1) * DD));
        float4 w2 = __ldg((const float4*)(W + (4 * dq + 2) * DD));
        float4 w3 = __ldg((const float4*)(W + (4 * dq + 3) * DD));
        y0 += a0 * w0.x + a1 * w1.x + a2 * w2.x + a3 * w3.x;
        y1 += a0 * w0.y + a1 * w1.y + a2 * w2.y + a3 * w3.y;
        y2 += a0 * w0.z + a1 * w1.z + a2 * w2.z + a3 * w3.z;
        y3 += a0 * w0.w + a1 * w1.w + a2 * w2.w + a3 * w3.w;
    }

    float* dst = &g_vacc[g][p * DD] + lane * 4;
    atomicAdd(dst + 0, y0); atomicAdd(dst + 1, y1);
    atomicAdd(dst + 2, y2); atomicAdd(dst + 3, y3);
    __threadfence();
    atomicAdd(&g_cnt[g][p], 1);     // every lane: target = cc*32
}

// =============== fold root transform + dscore ===============
__global__ void k_fold(const int* __restrict__ posp,
                       const float* __restrict__ ew,
                       const float* __restrict__ eb,
                       const float* __restrict__ sew,
                       const float* __restrict__ sdw,
                       const float* __restrict__ sb) {
    __shared__ float ss[DD];
    __shared__ float red[DD];
    int g = blockIdx.x, t = threadIdx.x;
    int er = g_pedge[g][g_plen[g] - 1];
    ss[t] = sew[t];
    __syncthreads();
    const float4* Wr = (const float4*)(ew + (size_t)er * (DD * DD) + t * DD);
    float acc = 0.f;
#pragma unroll 8
    for (int q = 0; q < 32; q++) {
        float4 wq = __ldg(Wr + q);
        acc += wq.x * ss[4 * q] + wq.y * ss[4 * q + 1]
             + wq.z * ss[4 * q + 2] + wq.w * ss[4 * q + 3];
    }
    g_w2[g][t] = acc;
    red[t] = eb[er * DD + t] * ss[t];
    __syncthreads();
    for (int s = 64; s > 0; s >>= 1) {
        if (t < s) red[t] += red[t + s];
        __syncthreads();
    }
    if (t == 0) g_cconst[g] = red[0];

    if (g == 0) {       // dscore in CTA 0
        __syncthreads();
        int pos = *posp;
        red[t] = g_base[pos * DD + t] * sdw[t];
        __syncthreads();
        for (int s = 64; s > 0; s >>= 1) {
            if (t < s) red[t] += red[t + s];
            __syncthreads();
        }
        if (t == 0) g_dscore = red[0] + sb[0];
    }
}

// =============== step0: y0[g][e] = relu?(vacc[g][pos]) @ W[e] + b[e] ===============
__global__ void __launch_bounds__(128)
k_step0(const int* __restrict__ posp,
        const float* __restrict__ ew,
        const float* __restrict__ eb) {
    __shared__ float s_v[NG][DD];
    int e = blockIdx.x, k = threadIdx.x;
    int pos = *posp;
#pragma unroll
    for (int g = 0; g < NG; g++) {
        float v = __ldcg(&g_vacc[g][pos * DD + k]);
        if (g_cc[g][pos] > 0) v = fmaxf(v, 0.f);
        s_v[g][k] = v;
    }
    __syncthreads();
    const float* W = ew + (size_t)e * (DD * DD);
    float acc[NG];
#pragma unroll
    for (int g = 0; g < NG; g++) acc[g] = 0.f;
#pragma unroll 8
    for (int d = 0; d < DD; d++) {
        float wv = __ldg(W + d * DD + k);
#pragma unroll
        for (int g = 0; g < NG; g++) acc[g] += s_v[g][d] * wv;
    }
    float b = eb[e * DD + k];
#pragma unroll
    for (int g = 0; g < NG; g++) g_y0[g][e * DD + k] = acc[g] + b;
}

// =============== path chains: 8 CTAs/graph, 16 chains/CTA, 4 chains/warp ===============
__global__ void __launch_bounds__(128)
k_chain(const float* __restrict__ ew,
        const float* __restrict__ eb,
        const float* __restrict__ sw,
        float* __restrict__ out) {
    __shared__ __align__(16) float s_m[4][2][DD][4];   // [warp][buf][d][chain]
    int g = blockIdx.x >> 3, blk = blockIdx.x & 7;
    int wp = threadIdx.x >> 5, lane = threadIdx.x & 31;
    int k0 = lane * 4;
    int ebase = blk * 16 + wp * 4;
    int plen = g_plen[g];
    float dscore = g_dscore;

    if (plen == 1) {
        float4 sv = *(const float4*)(sw + k0);
#pragma unroll
        for (int c = 0; c < 4; c++) {
            float4 y = *(const float4*)(&g_y0[g][(ebase + c) * DD + k0]);
            float p = y.x * sv.x + y.y * sv.y + y.z * sv.z + y.w * sv.w;
            for (int o = 16; o; o >>= 1) p += __shfl_xor_sync(0xffffffffu, p, o);
            if (lane == 0) out[g * EE + ebase + c] = dscore + p;
        }
        return;
    }

    // init m1 = relu(y0 + u1)
    {
        const float* u1 = &g_vacc[g][g_plist[g][1] * DD];
        float4 u4 = *(const float4*)(u1 + k0);
#pragma unroll
        for (int c = 0; c < 4; c++) {
            float4 y = *(const float4*)(&g_y0[g][(ebase + c) * DD + k0]);
            s_m[wp][0][k0 + 0][c] = fmaxf(y.x + u4.x, 0.f);
            s_m[wp][0][k0 + 1][c] = fmaxf(y.y + u4.y, 0.f);
            s_m[wp][0][k0 + 2][c] = fmaxf(y.z + u4.z, 0.f);
            s_m[wp][0][k0 + 3][c] = fmaxf(y.w + u4.w, 0.f);
        }
    }
    __syncwarp();

    int cur = 0;
    for (int i = 2; i < plen; i++) {
        int eid = g_pedge[g][i - 1];
        const float* W = ew + (size_t)eid * (DD * DD) + k0;
        float4 bv = *(const float4*)(eb + eid * DD + k0);
        float a[4][4];
#pragma unroll
        for (int c = 0; c < 4; c++) {
            a[c][0] = bv.x; a[c][1] = bv.y; a[c][2] = bv.z; a[c][3] = bv.w;
        }
#pragma unroll 8
        for (int d = 0; d < DD; d++) {
            float4 wv = __ldg((const float4*)(W + d * DD));
            float4 mv = *(const float4*)&s_m[wp][cur][d][0];
            a[0][0] += mv.x * wv.x; a[0][1] += mv.x * wv.y; a[0][2] += mv.x * wv.z; a[0][3] += mv.x * wv.w;
            a[1][0] += mv.y * wv.x; a[1][1] += mv.y * wv.y; a[1][2] += mv.y * wv.z; a[1][3] += mv.y * wv.w;
            a[2][0] += mv.z * wv.x; a[2][1] += mv.z * wv.y; a[2][2] += mv.z * wv.z; a[2][3] += mv.z * wv.w;
            a[3][0] += mv.w * wv.x; a[3][1] += mv.w * wv.y; a[3][2] += mv.w * wv.z; a[3][3] += mv.w * wv.w;
        }
        float4 u4 = *(const float4*)(&g_vacc[g][g_plist[g][i] * DD] + k0);
        __syncwarp();
#pragma unroll
        for (int c = 0; c < 4; c++) {
            s_m[wp][cur ^ 1][k0 + 0][c] = fmaxf(u4.x + a[c][0], 0.f);
            s_m[wp][cur ^ 1][k0 + 1][c] = fmaxf(u4.y + a[c][1], 0.f);
            s_m[wp][cur ^ 1][k0 + 2][c] = fmaxf(u4.z + a[c][2], 0.f);
            s_m[wp][cur ^ 1][k0 + 3][c] = fmaxf(u4.w + a[c][3], 0.f);
        }
        __syncwarp();
        cur ^= 1;
    }

    float4 w2v = *(const float4*)(&g_w2[g][0] + k0);
    float cc = g_cconst[g];
#pragma unroll
    for (int c = 0; c < 4; c++) {
        float p = s_m[wp][cur][k0 + 0][c] * w2v.x + s_m[wp][cur][k0 + 1][c] * w2v.y
                + s_m[wp][cur][k0 + 2][c] * w2v.z + s_m[wp][cur][k0 + 3][c] * w2v.w;
        for (int o = 16; o; o >>= 1) p += __shfl_xor_sync(0xffffffffu, p, o);
        if (lane == 0) out[g * EE + ebase + c] = dscore + cc + p;
    }
}

// =============== launcher ===============
extern "C" void kernel_launch(void* const* d_in, const int* in_sizes, int n_in,
                              void* d_out, int out_size) {
    const int*   data   = (const int*)d_in[0];
    const int*   graphs = (const int*)d_in[2];
    const int*   edges  = (const int*)d_in[3];
    const int*   pos    = (const int*)d_in[4];
    const float* dv     = (const float*)d_in[5];
    const float* dw     = (const float*)d_in[6];
    const float* db     = (const float*)d_in[7];
    const float* ew     = (const float*)d_in[8];
    const float* ebias  = (const float*)d_in[9];
    const float* sew    = (const float*)d_in[10];
    const float* sdw    = (const float*)d_in[11];
    const float* sb     = (const float*)d_in[12];
    float* out = (float*)d_out;

    k_parse  <<<NG, NN>>>(graphs, edges, pos);
    k_base   <<<NN, DD>>>(data, dv, dw, db);
    k_vecflow<<<128, 256>>>(edges, ew, ebias);
    k_fold   <<<NG, DD>>>(pos, ew, ebias, sew, sdw, sb);
    k_step0  <<<EE, 128>>>(pos, ew, ebias);
    k_chain  <<<NG * 8, 128>>>(ew, ebias, sew, out);
}